// round 2
// baseline (speedup 1.0000x reference)
#include <cuda_runtime.h>
#include <math.h>

// Problem constants
#define Bsz    64
#define Ssz    512
#define Hsz    256
#define Dsz    207
#define DINsz  414

// Partition: 4 batch-groups x 32 hidden-groups = 128 blocks
#define GRID    128
#define THREADS 256
#define NB      16        // batch per block
#define NI      8         // hidden units per block
#define NROWB   24        // 3*NI gate rows
#define XS_STR  420       // 414 padded; 420 % 32 == 4 -> conflict-free LDS.128
#define HS_STR  260       // 256 padded; 260 % 32 == 4

// Persistent global state (device globals: no runtime allocation)
__device__ float    g_h[Bsz * Hsz];
__device__ float    g_xh[Bsz * Dsz];
__device__ unsigned g_flags[GRID * 8];   // one flag per block, 32B apart

__device__ __forceinline__ void grid_bar(unsigned target) {
    __syncthreads();
    if (threadIdx.x == 0) {
        asm volatile("st.release.gpu.u32 [%0], %1;"
                     :: "l"(g_flags + blockIdx.x * 8), "r"(target) : "memory");
    }
    if (threadIdx.x < GRID) {
        const unsigned* p = g_flags + threadIdx.x * 8;
        unsigned v;
        do {
            asm volatile("ld.acquire.gpu.u32 %0, [%1];" : "=r"(v) : "l"(p) : "memory");
        } while ((int)(v - target) < 0);
    }
    __threadfence();   // membar.gpu: no stale L1 for subsequent weak loads
    __syncthreads();
}

__device__ __forceinline__ void fma4(float4& acc, const float4 wgt, const float4 xv) {
    acc.x = fmaf(wgt.x, xv.x, acc.x);
    acc.y = fmaf(wgt.y, xv.y, acc.y);
    acc.z = fmaf(wgt.z, xv.z, acc.z);
    acc.w = fmaf(wgt.w, xv.w, acc.w);
}

__global__ void __launch_bounds__(THREADS, 1)
rnn_imputer_kernel(const float* __restrict__ x, const float* __restrict__ mask,
                   const float* __restrict__ Wih, const float* __restrict__ Whh,
                   const float* __restrict__ bih, const float* __restrict__ bhh,
                   const float* __restrict__ Wro, const float* __restrict__ bro,
                   float* __restrict__ out)
{
    extern __shared__ float sm[];
    float* wih_s = sm;                        // 24*420  W_ih slice, K-padded
    float* wa_s  = wih_s + NROWB * XS_STR;    // 31*260  W_hh rows (0..23) + W_ro rows (24..)
    float* xs    = wa_s + 31 * HS_STR;        // 16*420  x_in staging
    float* hs    = xs + NB * XS_STR;          // 16*260  h staging
    float* gi_s  = hs + NB * HS_STR;          // 16*24
    float* gh_s  = gi_s + NB * NROWB;         // 16*24
    float* bih_s = gh_s + NB * NROWB;         // 24
    float* bhh_s = bih_s + NROWB;             // 24
    float* bro_s = bhh_s + NROWB;             // 8

    const int tid = threadIdx.x, blk = blockIdx.x;
    const int bg = blk >> 5, ig = blk & 31;
    const int b0 = bg * NB;                   // global batch base
    const int i0 = ig * NI;                   // global hidden base
    const int d0 = ig * 6 + (ig < 15 ? ig : 15);   // readout dim range
    const int nd = (ig < 15) ? 7 : 6;
    const int NROWA = NROWB + nd;

    // ---- one-time weight staging ----
    for (int idx = tid; idx < NROWB * DINsz; idx += THREADS) {
        int r = idx / DINsz, k = idx - r * DINsz;
        int ii = r / 3, g = r - ii * 3;
        wih_s[r * XS_STR + k] = Wih[(g * Hsz + i0 + ii) * DINsz + k];
    }
    for (int idx = tid; idx < NROWB * (XS_STR - DINsz); idx += THREADS) {
        int r = idx / 6, c = idx - r * 6;
        wih_s[r * XS_STR + DINsz + c] = 0.f;
    }
    for (int idx = tid; idx < NROWB * Hsz; idx += THREADS) {
        int r = idx >> 8, k = idx & 255;
        int ii = r / 3, g = r - ii * 3;
        wa_s[r * HS_STR + k] = Whh[(g * Hsz + i0 + ii) * Hsz + k];
    }
    for (int idx = tid; idx < nd * Hsz; idx += THREADS) {
        int r = idx >> 8, k = idx & 255;
        wa_s[(NROWB + r) * HS_STR + k] = Wro[(d0 + r) * Hsz + k];
    }
    for (int idx = tid; idx < 31 * 4; idx += THREADS)
        wa_s[(idx >> 2) * HS_STR + Hsz + (idx & 3)] = 0.f;
    for (int idx = tid; idx < NB * 6; idx += THREADS)
        xs[(idx / 6) * XS_STR + DINsz + (idx % 6)] = 0.f;
    for (int idx = tid; idx < NB * 4; idx += THREADS)
        hs[(idx >> 2) * HS_STR + Hsz + (idx & 3)] = 0.f;
    if (tid < NROWB) {
        int ii = tid / 3, g = tid - ii * 3;
        bih_s[tid] = bih[g * Hsz + i0 + ii];
        bhh_s[tid] = bhh[g * Hsz + i0 + ii];
    }
    if (tid < nd) bro_s[tid] = bro[d0 + tid];

    // zero my slice of h state
    if (tid < NB * NI) {
        int b = tid >> 3, ii = tid & 7;
        g_h[(b0 + b) * Hsz + i0 + ii] = 0.f;
    }

    // barrier generation base (monotonic across graph replays)
    unsigned base = *(volatile unsigned*)(g_flags + blk * 8);
    unsigned barnum = 0;

    grid_bar(base + (++barnum));   // init complete

    const int lane = tid & 31, warp = tid >> 5;
    const int lb = lane & 15, kh = lane >> 4;   // (batch, k-half) lane layout

    for (int t = 0; t < Ssz; ++t) {
        // ================= PHASE A: gh = h@Whh^T ; xh = h@Wro^T + b_ro =================
        for (int idx = tid; idx < NB * 64; idx += THREADS) {
            int b = idx >> 6, c = idx & 63;
            float4 v = __ldcg(reinterpret_cast<const float4*>(g_h + (b0 + b) * Hsz + c * 4));
            *reinterpret_cast<float4*>(hs + b * HS_STR + c * 4) = v;
        }
        __syncthreads();
        {
            const int r0 = warp * 4;                  // 4 rows per warp, 32 row-slots
            float4 acc[4];
#pragma unroll
            for (int j = 0; j < 4; ++j) acc[j] = make_float4(0.f, 0.f, 0.f, 0.f);
            const float4* xp = reinterpret_cast<const float4*>(hs + lb * HS_STR) + kh;
            const float4* wp[4];
#pragma unroll
            for (int j = 0; j < 4; ++j)
                wp[j] = reinterpret_cast<const float4*>(wa_s + (r0 + j) * HS_STR) + kh;
#pragma unroll 8
            for (int kk = 0; kk < 32; ++kk) {
                float4 xv = xp[2 * kk];
#pragma unroll
                for (int j = 0; j < 4; ++j) { float4 wv = wp[j][2 * kk]; fma4(acc[j], wv, xv); }
            }
#pragma unroll
            for (int j = 0; j < 4; ++j) {
                float s = (acc[j].x + acc[j].y) + (acc[j].z + acc[j].w);
                s += __shfl_xor_sync(0xffffffffu, s, 16);
                int row = r0 + j;
                if (lane < 16 && row < NROWA) {
                    if (row < NROWB) {
                        gh_s[lb * NROWB + row] = s;
                    } else {
                        int dd = row - NROWB;
                        int d = d0 + dd, gb = b0 + lb;
                        float v = s + bro_s[dd];
                        g_xh[gb * Dsz + d] = v;
                        out[((size_t)gb * Ssz + t) * Dsz + d] = v;
                    }
                }
            }
        }
        grid_bar(base + (++barnum));
        if (t == Ssz - 1) break;

        // ================= PHASE B: gi = x_in@Wih^T ; gates ; h_new =================
        for (int idx = tid; idx < NB * Dsz; idx += THREADS) {
            int b = idx / Dsz, k = idx - b * Dsz;
            int gb = b0 + b;
            size_t o = ((size_t)gb * Ssz + t) * Dsz + k;
            float xv = x[o], mv = mask[o];
            float xhv = __ldcg(g_xh + gb * Dsz + k);
            xs[b * XS_STR + k] = (mv > 0.5f) ? xv : xhv;
            xs[b * XS_STR + Dsz + k] = mv;
        }
        __syncthreads();
        {
            const int r0 = warp * 3;                  // 3 rows per warp = one hidden unit
            float4 acc[3];
#pragma unroll
            for (int j = 0; j < 3; ++j) acc[j] = make_float4(0.f, 0.f, 0.f, 0.f);
            const float4* xp = reinterpret_cast<const float4*>(xs + lb * XS_STR) + kh;
            const float4* wp[3];
#pragma unroll
            for (int j = 0; j < 3; ++j)
                wp[j] = reinterpret_cast<const float4*>(wih_s + (r0 + j) * XS_STR) + kh;
#pragma unroll 4
            for (int kk = 0; kk < 52; ++kk) {         // 52*8 = 416 >= 414 (zero padded)
                float4 xv = xp[2 * kk];
#pragma unroll
                for (int j = 0; j < 3; ++j) { float4 wv = wp[j][2 * kk]; fma4(acc[j], wv, xv); }
            }
#pragma unroll
            for (int j = 0; j < 3; ++j) {
                float s = (acc[j].x + acc[j].y) + (acc[j].z + acc[j].w);
                s += __shfl_xor_sync(0xffffffffu, s, 16);
                if (lane < 16) gi_s[lb * NROWB + (r0 + j)] = s;
            }
        }
        __syncthreads();
        if (tid < NB * NI) {
            int b = tid >> 3, ii = tid & 7;
            int r3 = ii * 3;
            float ir  = gi_s[b * NROWB + r3]     + bih_s[r3];
            float iz  = gi_s[b * NROWB + r3 + 1] + bih_s[r3 + 1];
            float inn = gi_s[b * NROWB + r3 + 2] + bih_s[r3 + 2];
            float hr  = gh_s[b * NROWB + r3]     + bhh_s[r3];
            float hz  = gh_s[b * NROWB + r3 + 1] + bhh_s[r3 + 1];
            float hn  = gh_s[b * NROWB + r3 + 2] + bhh_s[r3 + 2];
            float r = 1.f / (1.f + expf(-(ir + hr)));
            float z = 1.f / (1.f + expf(-(iz + hz)));
            float n = tanhf(inn + r * hn);
            float hold = hs[b * HS_STR + i0 + ii];
            g_h[(b0 + b) * Hsz + i0 + ii] = (1.f - z) * n + z * hold;
        }
        grid_bar(base + (++barnum));
    }
}

static const int SMEM_BYTES =
    (NROWB * XS_STR + 31 * HS_STR + NB * XS_STR + NB * HS_STR +
     2 * NB * NROWB + 2 * NROWB + 8) * (int)sizeof(float);

extern "C" void kernel_launch(void* const* d_in, const int* in_sizes, int n_in,
                              void* d_out, int out_size) {
    const float* x    = (const float*)d_in[0];
    const float* mask = (const float*)d_in[1];
    const float* Wih  = (const float*)d_in[2];
    const float* Whh  = (const float*)d_in[3];
    const float* bih  = (const float*)d_in[4];
    const float* bhh  = (const float*)d_in[5];
    const float* Wro  = (const float*)d_in[6];
    const float* bro  = (const float*)d_in[7];
    float* out = (float*)d_out;

    cudaFuncSetAttribute(rnn_imputer_kernel,
                         cudaFuncAttributeMaxDynamicSharedMemorySize, SMEM_BYTES);
    rnn_imputer_kernel<<<GRID, THREADS, SMEM_BYTES>>>(x, mask, Wih, Whh, bih, bhh,
                                                      Wro, bro, out);
}

// round 3
// speedup vs baseline: 1.1403x; 1.1403x over previous
#include <cuda_runtime.h>
#include <math.h>

// Problem constants
#define Bsz    64
#define Ssz    512
#define Hsz    256
#define Dsz    207
#define DINsz  414

// Partition: 4 batch-groups x 32 hidden-groups = 128 blocks
#define GRID    128
#define THREADS 256
#define NB      16        // batch per block
#define NI      8         // hidden units per block
#define NROWB   24        // 3*NI gate rows
#define XS_STR  420       // 414 padded; 420 % 32 == 4 -> conflict-free LDS.128
#define HS_STR  260       // 256 padded; 260 % 32 == 4

// Persistent global state (device globals: no runtime allocation)
__device__ float    g_h[Bsz * Hsz];
__device__ float    g_xh[Bsz * Dsz];
__device__ unsigned g_flags[GRID * 8];   // one flag per block, 32B apart

// Split-phase group barrier: release own flag, later wait on the 32 flags of
// this batch-group. st.release/ld.acquire chain + bar.sync = CG grid.sync
// pattern; no membar needed (all cross-block data read via L2: __ldcg / fresh
// global loads after acquire).
__device__ __forceinline__ void bar_release(unsigned target) {
    __syncthreads();
    if (threadIdx.x == 0) {
        asm volatile("st.release.gpu.u32 [%0], %1;"
                     :: "l"(g_flags + blockIdx.x * 8), "r"(target) : "memory");
    }
}
__device__ __forceinline__ void bar_wait(int gbase, unsigned target) {
    if (threadIdx.x < 32) {
        const unsigned* p = g_flags + (gbase + threadIdx.x) * 8;
        unsigned v;
        do {
            asm volatile("ld.acquire.gpu.u32 %0, [%1];" : "=r"(v) : "l"(p) : "memory");
        } while ((int)(v - target) < 0);
    }
    __syncthreads();
}

__device__ __forceinline__ void fma4(float4& acc, const float4 wgt, const float4 xv) {
    acc.x = fmaf(wgt.x, xv.x, acc.x);
    acc.y = fmaf(wgt.y, xv.y, acc.y);
    acc.z = fmaf(wgt.z, xv.z, acc.z);
    acc.w = fmaf(wgt.w, xv.w, acc.w);
}

__global__ void __launch_bounds__(THREADS, 1)
rnn_imputer_kernel(const float* __restrict__ x, const float* __restrict__ mask,
                   const float* __restrict__ Wih, const float* __restrict__ Whh,
                   const float* __restrict__ bih, const float* __restrict__ bhh,
                   const float* __restrict__ Wro, const float* __restrict__ bro,
                   float* __restrict__ out)
{
    extern __shared__ float sm[];
    float* wih_s = sm;                        // 24*420  W_ih slice, K-padded
    float* wa_s  = wih_s + NROWB * XS_STR;    // 31*260  W_hh rows (0..23) + W_ro rows (24..)
    float* xs    = wa_s + 31 * HS_STR;        // 16*420  x_in staging
    float* hs    = xs + NB * XS_STR;          // 16*260  h staging
    float* gi_s  = hs + NB * HS_STR;          // 16*24
    float* gh_s  = gi_s + NB * NROWB;         // 16*24
    float* bih_s = gh_s + NB * NROWB;         // 24
    float* bhh_s = bih_s + NROWB;             // 24
    float* bro_s = bhh_s + NROWB;             // 8

    const int tid = threadIdx.x, blk = blockIdx.x;
    const int bg = blk >> 5, ig = blk & 31;
    const int gbase = bg << 5;                // first block of my barrier group
    const int b0 = bg * NB;                   // global batch base
    const int i0 = ig * NI;                   // global hidden base
    const int d0 = ig * 6 + (ig < 15 ? ig : 15);   // readout dim range
    const int nd = (ig < 15) ? 7 : 6;

    // ---- one-time weight staging ----
    for (int idx = tid; idx < NROWB * DINsz; idx += THREADS) {
        int r = idx / DINsz, k = idx - r * DINsz;
        int ii = r / 3, g = r - ii * 3;
        wih_s[r * XS_STR + k] = Wih[(g * Hsz + i0 + ii) * DINsz + k];
    }
    for (int idx = tid; idx < NROWB * (XS_STR - DINsz); idx += THREADS) {
        int r = idx / 6, c = idx - r * 6;
        wih_s[r * XS_STR + DINsz + c] = 0.f;
    }
    for (int idx = tid; idx < NROWB * Hsz; idx += THREADS) {
        int r = idx >> 8, k = idx & 255;
        int ii = r / 3, g = r - ii * 3;
        wa_s[r * HS_STR + k] = Whh[(g * Hsz + i0 + ii) * Hsz + k];
    }
    for (int idx = tid; idx < nd * Hsz; idx += THREADS) {
        int r = idx >> 8, k = idx & 255;
        wa_s[(NROWB + r) * HS_STR + k] = Wro[(d0 + r) * Hsz + k];
    }
    for (int idx = tid; idx < NB * 6; idx += THREADS)
        xs[(idx / 6) * XS_STR + DINsz + (idx % 6)] = 0.f;
    for (int idx = tid; idx < NB * 4; idx += THREADS)
        hs[(idx >> 2) * HS_STR + Hsz + (idx & 3)] = 0.f;
    if (tid < NROWB) {
        int ii = tid / 3, g = tid - ii * 3;
        bih_s[tid] = bih[g * Hsz + i0 + ii];
        bhh_s[tid] = bhh[g * Hsz + i0 + ii];
    }
    if (tid < nd) bro_s[tid] = bro[d0 + tid];

    // prefetch x[0], mask[0] into xs
    for (int idx = tid; idx < NB * Dsz; idx += THREADS) {
        int b = idx / Dsz, k = idx - b * Dsz;
        size_t o = ((size_t)(b0 + b) * Ssz) * Dsz + k;
        xs[b * XS_STR + k] = x[o];
        xs[b * XS_STR + Dsz + k] = mask[o];
    }

    // zero my slice of h state
    if (tid < NB * NI) {
        int b = tid >> 3, ii = tid & 7;
        g_h[(b0 + b) * Hsz + i0 + ii] = 0.f;
    }

    // barrier generation base (monotonic across graph replays)
    unsigned base = *(volatile unsigned*)(g_flags + blk * 8);
    unsigned cnt = 0;

    bar_release(base + (++cnt));
    bar_wait(gbase, base + cnt);    // init complete (group scope)

    const int lane = tid & 31, warp = tid >> 5;
    const int lb = lane & 15, kh = lane >> 4;   // (batch, k-half) lane layout

    for (int t = 0; t < Ssz; ++t) {
        // ---- load h_t into SMEM ----
        for (int idx = tid; idx < NB * 64; idx += THREADS) {
            int b = idx >> 6, c = idx & 63;
            float4 v = __ldcg(reinterpret_cast<const float4*>(g_h + (b0 + b) * Hsz + c * 4));
            *reinterpret_cast<float4*>(hs + b * HS_STR + c * 4) = v;
        }
        __syncthreads();

        // ---- A1: readout rows FIRST (x_hat needed by peers) ----
        if (warp < nd) {
            const int row = NROWB + warp;
            float4 acc = make_float4(0.f, 0.f, 0.f, 0.f);
            const float4* xp = reinterpret_cast<const float4*>(hs + lb * HS_STR) + kh;
            const float4* wp = reinterpret_cast<const float4*>(wa_s + row * HS_STR) + kh;
#pragma unroll 8
            for (int kk = 0; kk < 32; ++kk) {
                float4 xv = xp[2 * kk];
                float4 wv = wp[2 * kk];
                fma4(acc, wv, xv);
            }
            float s = (acc.x + acc.y) + (acc.z + acc.w);
            s += __shfl_xor_sync(0xffffffffu, s, 16);
            if (lane < 16) {
                int d = d0 + warp, gb = b0 + lb;
                float v = s + bro_s[warp];
                g_xh[gb * Dsz + d] = v;
                out[((size_t)gb * Ssz + t) * Dsz + d] = v;
            }
        }
        if (t == Ssz - 1) break;          // last step: only readout needed
        bar_release(base + (++cnt));      // publish x_hat (syncthreads inside)

        // ---- A2: gh = h @ Whh^T (overlaps barrier A) ----
        {
            const int r0 = warp * 3;
            float4 acc[3];
#pragma unroll
            for (int j = 0; j < 3; ++j) acc[j] = make_float4(0.f, 0.f, 0.f, 0.f);
            const float4* xp = reinterpret_cast<const float4*>(hs + lb * HS_STR) + kh;
            const float4* wp[3];
#pragma unroll
            for (int j = 0; j < 3; ++j)
                wp[j] = reinterpret_cast<const float4*>(wa_s + (r0 + j) * HS_STR) + kh;
#pragma unroll 8
            for (int kk = 0; kk < 32; ++kk) {
                float4 xv = xp[2 * kk];
#pragma unroll
                for (int j = 0; j < 3; ++j) { float4 wv = wp[j][2 * kk]; fma4(acc[j], wv, xv); }
            }
#pragma unroll
            for (int j = 0; j < 3; ++j) {
                float s = (acc[j].x + acc[j].y) + (acc[j].z + acc[j].w);
                s += __shfl_xor_sync(0xffffffffu, s, 16);
                if (lane < 16) gh_s[lb * NROWB + (r0 + j)] = s;
            }
        }
        bar_wait(gbase, base + cnt);      // x_hat from peers ready

        // ---- B0: patch unobserved entries with x_hat ----
        for (int idx = tid; idx < NB * Dsz; idx += THREADS) {
            int b = idx / Dsz, k = idx - b * Dsz;
            float mv = xs[b * XS_STR + Dsz + k];
            if (mv <= 0.5f)
                xs[b * XS_STR + k] = __ldcg(g_xh + (b0 + b) * Dsz + k);
        }
        __syncthreads();

        // ---- B1: gi = x_in @ Wih^T ----
        {
            const int r0 = warp * 3;
            float4 acc[3];
#pragma unroll
            for (int j = 0; j < 3; ++j) acc[j] = make_float4(0.f, 0.f, 0.f, 0.f);
            const float4* xp = reinterpret_cast<const float4*>(xs + lb * XS_STR) + kh;
            const float4* wp[3];
#pragma unroll
            for (int j = 0; j < 3; ++j)
                wp[j] = reinterpret_cast<const float4*>(wih_s + (r0 + j) * XS_STR) + kh;
#pragma unroll 4
            for (int kk = 0; kk < 52; ++kk) {          // 52*8 = 416 >= 414 (zero padded)
                float4 xv = xp[2 * kk];
#pragma unroll
                for (int j = 0; j < 3; ++j) { float4 wv = wp[j][2 * kk]; fma4(acc[j], wv, xv); }
            }
#pragma unroll
            for (int j = 0; j < 3; ++j) {
                float s = (acc[j].x + acc[j].y) + (acc[j].z + acc[j].w);
                s += __shfl_xor_sync(0xffffffffu, s, 16);
                if (lane < 16) gi_s[lb * NROWB + (r0 + j)] = s;
            }
        }
        __syncthreads();

        // ---- B2: gates -> h_new ----
        if (tid < NB * NI) {
            int b = tid >> 3, ii = tid & 7;
            int r3 = ii * 3;
            float ir  = gi_s[b * NROWB + r3]     + bih_s[r3];
            float iz  = gi_s[b * NROWB + r3 + 1] + bih_s[r3 + 1];
            float inn = gi_s[b * NROWB + r3 + 2] + bih_s[r3 + 2];
            float hr  = gh_s[b * NROWB + r3]     + bhh_s[r3];
            float hz  = gh_s[b * NROWB + r3 + 1] + bhh_s[r3 + 1];
            float hn  = gh_s[b * NROWB + r3 + 2] + bhh_s[r3 + 2];
            float r = 1.f / (1.f + expf(-(ir + hr)));
            float z = 1.f / (1.f + expf(-(iz + hz)));
            float n = tanhf(inn + r * hn);
            float hold = hs[b * HS_STR + i0 + ii];
            g_h[(b0 + b) * Hsz + i0 + ii] = (1.f - z) * n + z * hold;
        }
        bar_release(base + (++cnt));      // publish h_new (syncthreads inside)

        // ---- prefetch x[t+1], mask[t+1] (overlaps barrier B) ----
        for (int idx = tid; idx < NB * Dsz; idx += THREADS) {
            int b = idx / Dsz, k = idx - b * Dsz;
            size_t o = ((size_t)(b0 + b) * Ssz + (t + 1)) * Dsz + k;
            xs[b * XS_STR + k] = x[o];
            xs[b * XS_STR + Dsz + k] = mask[o];
        }
        bar_wait(gbase, base + cnt);      // h_new from peers ready
    }
}

static const int SMEM_BYTES =
    (NROWB * XS_STR + 31 * HS_STR + NB * XS_STR + NB * HS_STR +
     2 * NB * NROWB + 2 * NROWB + 8) * (int)sizeof(float);

extern "C" void kernel_launch(void* const* d_in, const int* in_sizes, int n_in,
                              void* d_out, int out_size) {
    const float* x    = (const float*)d_in[0];
    const float* mask = (const float*)d_in[1];
    const float* Wih  = (const float*)d_in[2];
    const float* Whh  = (const float*)d_in[3];
    const float* bih  = (const float*)d_in[4];
    const float* bhh  = (const float*)d_in[5];
    const float* Wro  = (const float*)d_in[6];
    const float* bro  = (const float*)d_in[7];
    float* out = (float*)d_out;

    cudaFuncSetAttribute(rnn_imputer_kernel,
                         cudaFuncAttributeMaxDynamicSharedMemorySize, SMEM_BYTES);
    rnn_imputer_kernel<<<GRID, THREADS, SMEM_BYTES>>>(x, mask, Wih, Whh, bih, bhh,
                                                      Wro, bro, out);
}